// round 6
// baseline (speedup 1.0000x reference)
#include <cuda_runtime.h>

#define DIM 16

// Folded weights: out = chem @ M^T + c, where M = Wo @ Wv, c = Wo @ bv + bo
__device__ __align__(16) float g_M[DIM * DIM];  // M[j][i], row-major
__device__ __align__(16) float g_c[DIM];

// ---------------------------------------------------------------------------
// Tiny prep kernel: fold the two 16x16 matmuls + biases into one matrix.
// One block, 256 threads: thread (j,i) computes M[j][i].
// ---------------------------------------------------------------------------
__global__ void prep_kernel(const float* __restrict__ in_w,   // [48,16] (Wq|Wk|Wv)
                            const float* __restrict__ in_b,   // [48]
                            const float* __restrict__ out_w,  // [16,16]
                            const float* __restrict__ out_b)  // [16]
{
    const int t = threadIdx.x;           // 0..255
    const int j = t >> 4;
    const int i = t & 15;
    float s = 0.f;
#pragma unroll
    for (int k = 0; k < DIM; ++k)
        s += out_w[j * DIM + k] * in_w[(2 * DIM + k) * DIM + i];
    g_M[j * DIM + i] = s;
    if (i == 0) {
        float c = out_b[j];
#pragma unroll
        for (int k = 0; k < DIM; ++k)
            c += out_w[j * DIM + k] * in_b[2 * DIM + k];
        g_c[j] = c;
    }
}

// packed f32x2 FMA (Blackwell; only reachable via PTX)
__device__ __forceinline__ unsigned long long ffma2(unsigned long long a,
                                                    unsigned long long b,
                                                    unsigned long long c)
{
    unsigned long long d;
    asm("fma.rn.f32x2 %0, %1, %2, %3;" : "=l"(d) : "l"(a), "l"(b), "l"(c));
    return d;
}

// ---------------------------------------------------------------------------
// Main kernel: 8 threads per row, each computes 2 output columns.
// Weights (2 rows of M = 16 packed f32x2 regs) live in registers and are
// amortized over the whole grid-stride loop. Row loads are software-
// pipelined: next row's 4x LDG.128 are issued before computing the current
// row, giving per-thread MLP of 8 outstanding 16B loads.
// ---------------------------------------------------------------------------
__global__ void __launch_bounds__(256, 3)
matvec_kernel(const float* __restrict__ chem, float* __restrict__ out, int rows)
{
    const int g       = blockIdx.x * blockDim.x + threadIdx.x;
    const int e       = g & 7;            // which 2-column group of the row
    const int jg      = e * 2;            // first output column
    const int rstride = (gridDim.x * blockDim.x) >> 3;
    int r             = g >> 3;

    // Load this thread's 2 rows of M (32 weights) as 16 packed f32x2 regs.
    unsigned long long w0[8], w1[8];
    {
        const unsigned long long* wp0 =
            reinterpret_cast<const unsigned long long*>(&g_M[(jg + 0) * DIM]);
        const unsigned long long* wp1 =
            reinterpret_cast<const unsigned long long*>(&g_M[(jg + 1) * DIM]);
#pragma unroll
        for (int i2 = 0; i2 < 8; ++i2) { w0[i2] = wp0[i2]; w1[i2] = wp1[i2]; }
    }
    const float c0 = g_c[jg + 0];
    const float c1 = g_c[jg + 1];

    if (r >= rows) return;

    // Prefetch first row (streaming loads; data is touch-once).
    const ulonglong2* p =
        reinterpret_cast<const ulonglong2*>(chem + (size_t)r * DIM);
    ulonglong2 a0 = __ldcs(p + 0);
    ulonglong2 a1 = __ldcs(p + 1);
    ulonglong2 a2 = __ldcs(p + 2);
    ulonglong2 a3 = __ldcs(p + 3);

    for (;;) {
        const int rn = r + rstride;
        const bool more = rn < rows;

        // Issue next row's loads before touching this row's data.
        ulonglong2 b0, b1, b2, b3;
        if (more) {
            const ulonglong2* pn =
                reinterpret_cast<const ulonglong2*>(chem + (size_t)rn * DIM);
            b0 = __ldcs(pn + 0);
            b1 = __ldcs(pn + 1);
            b2 = __ldcs(pn + 2);
            b3 = __ldcs(pn + 3);
        }

        const unsigned long long ap[8] = {a0.x, a0.y, a1.x, a1.y,
                                          a2.x, a2.y, a3.x, a3.y};

        // col jg
        unsigned long long acc0 = (unsigned long long)__float_as_uint(c0);
        // col jg+1
        unsigned long long acc1 = (unsigned long long)__float_as_uint(c1);
#pragma unroll
        for (int i2 = 0; i2 < 8; ++i2) {
            acc0 = ffma2(ap[i2], w0[i2], acc0);
            acc1 = ffma2(ap[i2], w1[i2], acc1);
        }
        float2 res;
        res.x = __uint_as_float((unsigned int)acc0) +
                __uint_as_float((unsigned int)(acc0 >> 32));
        res.y = __uint_as_float((unsigned int)acc1) +
                __uint_as_float((unsigned int)(acc1 >> 32));

        // 8 threads cover the row with contiguous 8B stores (256B/warp).
        __stcs(reinterpret_cast<float2*>(out + (size_t)r * DIM) + e, res);

        if (!more) break;
        a0 = b0; a1 = b1; a2 = b2; a3 = b3;
        r = rn;
    }
}

extern "C" void kernel_launch(void* const* d_in, const int* in_sizes, int n_in,
                              void* d_out, int out_size)
{
    // inputs: 0=fp_16 (UNUSED), 1=chem_16, 2=in_proj_weight, 3=in_proj_bias,
    //         4=out_proj_weight, 5=out_proj_bias
    const float* chem  = (const float*)d_in[1];
    const float* in_w  = (const float*)d_in[2];
    const float* in_b  = (const float*)d_in[3];
    const float* out_w = (const float*)d_in[4];
    const float* out_b = (const float*)d_in[5];
    float* out = (float*)d_out;

    const int rows = in_sizes[1] / DIM;   // 2,097,152

    prep_kernel<<<1, 256>>>(in_w, in_b, out_w, out_b);

    // One-wave persistent grid: 148 SMs x 3 blocks (launch_bounds(256,3)).
    int blocks = 148 * 3;
    long long need = ((long long)rows * 8 + 255) / 256;
    if (need < blocks) blocks = (int)need;
    matvec_kernel<<<blocks, 256>>>(chem, out, rows);
}